// round 14
// baseline (speedup 1.0000x reference)
#include <cuda_runtime.h>
#include <cuda_bf16.h>
#include <math.h>

#define NB     32
#define NEV    393216
#define NSEG   48
#define SEGLEN 8192
#define WID    320
#define HEI    240
#define HW     76800
#define NWORD  2400        // HW/32
#define SIDX_C 4
#define EIDX_C 38
#define ROWS_USED 34       // rows 4..37 (row index 0..33)
#define NSTEP  33
#define WBLK   10          // word-blocks per batch (10*256 >= 2400)
#define SENT   0xFFFFFFFFFFFFFFFFull

// ---------------- device scratch ----------------
__device__ int                g_mom[NB * NSEG * 10];
__device__ unsigned           g_packed[(size_t)NB * ROWS_USED * SEGLEN]; // (y<<9)|x
__device__ int                g_aligned[NB * NSEG * 2];
__device__ unsigned long long g_actmask[NB];
__device__ unsigned long long g_ctb[NB];                  // contrib mask (sentinel-published)
__device__ unsigned long long g_apl[NB];                  // applied mask
__device__ int                g_done2[NB];
__device__ int                g_cnt[NB * ROWS_USED];
__device__ int                g_stat[NB * 4];   // conf sum, conf sq, cont sum, cont sq (int exact)
__device__ unsigned           g_raw[(size_t)NB * ROWS_USED * NWORD];     // per-row bitmaps
__device__ unsigned char      g_hist8[(size_t)NB * ROWS_USED * HW];      // per-row byte counts
__device__ unsigned char      g_conf8[(size_t)NB * HW];
__device__ int                g_cont[(size_t)NB * HW];

// ---------------- K1: histogram moments + packed coords ----------------
__global__ void __launch_bounds__(256) k_hist(const int* __restrict__ ev) {
    __shared__ int shx[WID];
    __shared__ int shy[HEI];
    __shared__ int sm1x, sm1y;
    int bx = blockIdx.x;
    int b = bx / NSEG, s = bx % NSEG;
    int t = threadIdx.x;

    for (int e = t; e < WID; e += 256) shx[e] = 0;
    for (int e = t; e < HEI; e += 256) shy[e] = 0;
    if (t == 0) { sm1x = 0; sm1y = 0; }
    __syncthreads();

    const uint4* evv = (const uint4*)(ev + ((size_t)b * NEV + (size_t)s * SEGLEN) * 5);
    bool wr = (s >= SIDX_C && s < EIDX_C);
    int sp = s - SIDX_C; if (sp < 0) sp = 0;
    uint4* pk4 = (uint4*)(g_packed + ((size_t)b * ROWS_USED + sp) * SEGLEN);

    for (int g = t; g < SEGLEN / 4; g += 256) {
        uint4 a0 = evv[g * 5 + 0];
        uint4 a1 = evv[g * 5 + 1];
        uint4 a2 = evv[g * 5 + 2];
        uint4 a3 = evv[g * 5 + 3];
        uint4 a4 = evv[g * 5 + 4];
        int x0 = (int)a0.x, y0 = (int)a0.y;
        int x1 = (int)a1.y, y1 = (int)a1.z;
        int x2 = (int)a2.z, y2 = (int)a2.w;
        int x3 = (int)a3.w, y3 = (int)a4.x;
        atomicAdd(&shx[x0], 1); atomicAdd(&shy[y0], 1);
        atomicAdd(&shx[x1], 1); atomicAdd(&shy[y1], 1);
        atomicAdd(&shx[x2], 1); atomicAdd(&shy[y2], 1);
        atomicAdd(&shx[x3], 1); atomicAdd(&shy[y3], 1);
        if (wr) {
            uint4 p;
            p.x = (unsigned)((y0 << 9) | x0);
            p.y = (unsigned)((y1 << 9) | x1);
            p.z = (unsigned)((y2 << 9) | x2);
            p.w = (unsigned)((y3 << 9) | x3);
            pk4[g] = p;
        }
    }
    __syncthreads();

    int l1 = 0, l2 = 0;
    for (int e = t; e < WID; e += 256) l1 += e * shx[e];
    for (int e = t; e < HEI; e += 256) l2 += e * shy[e];
    for (int o = 16; o; o >>= 1) {
        l1 += __shfl_down_sync(0xffffffffu, l1, o);
        l2 += __shfl_down_sync(0xffffffffu, l2, o);
    }
    if ((t & 31) == 0) { atomicAdd(&sm1x, l1); atomicAdd(&sm1y, l2); }
    __syncthreads();

    if (t == 0) {
        int* mm = g_mom + (b * NSEG + s) * 10;
        mm[0] = sm1x; mm[1] = shx[0]; mm[2] = shx[1]; mm[3] = shx[WID - 2]; mm[4] = shx[WID - 1];
        mm[5] = sm1y; mm[6] = shy[0]; mm[7] = shy[1]; mm[8] = shy[HEI - 2]; mm[9] = shy[HEI - 1];
    }
}

// ---------------- K2: means + aligned + outlier flags -> active mask ----------------
__device__ __forceinline__ void sort10(float* a) {
    #pragma unroll
    for (int i = 1; i < 10; i++) {
        float v = a[i]; int j = i - 1;
        while (j >= 0 && a[j] > v) { a[j + 1] = a[j]; j--; }
        a[j + 1] = v;
    }
}

__device__ bool outl(const float* m, int i) {
    float w[10], s[10];
    #pragma unroll
    for (int t = 0; t < 10; t++) { w[t] = m[i + t]; s[t] = w[t]; }
    sort10(s);
    float med = 0.5f * (s[4] + s[5]);
    float d0 = fabsf(w[0] - med);
    float ds[10];
    #pragma unroll
    for (int t = 0; t < 10; t++) ds[t] = fabsf(w[t] - med);
    sort10(ds);
    float mad = 0.5f * (ds[4] + ds[5]);
    float mz = (0.6745f * d0) / mad;
    return mz > 3.0f;
}

__global__ void __launch_bounds__(128) k_mean(const float* __restrict__ kern) {
    __shared__ float skk[25];
    __shared__ float smX[NSEG], smY[NSEG];
    __shared__ unsigned char s_flag[NSTEP];
    int b = blockIdx.x, t = threadIdx.x;
    if (t < 25) skk[t] = kern[t];
    if (t < ROWS_USED) g_cnt[b * ROWS_USED + t] = 0;
    if (t < 4) g_stat[b * 4 + t] = 0;
    if (t == 0) { g_done2[b] = 0; g_ctb[b] = SENT; }
    __syncthreads();

    if (t < 96) {
        int coord = t / NSEG, s = t % NSEG;
        int D = coord ? HEI : WID;
        double num = 0.0;
        #pragma unroll
        for (int a = -2; a <= 2; a++) {
            int si = s + a;
            if (si < 0 || si >= NSEG) continue;
            const int* mm = g_mom + (b * NSEG + si) * 10 + coord * 5;
            double m1  = (double)mm[0];
            double h0  = (double)mm[1];
            double h1  = (double)mm[2];
            double hD2 = (double)mm[3];
            double hD1 = (double)mm[4];
            double kr0 = skk[(a + 2) * 5 + 0];
            double kr1 = skk[(a + 2) * 5 + 1];
            double kr2 = skk[(a + 2) * 5 + 2];
            double kr3 = skk[(a + 2) * 5 + 3];
            double kr4 = skk[(a + 2) * 5 + 4];
            double Ka = kr0 + kr1 + kr2 + kr3 + kr4;
            double Sb = -2.0 * kr0 - kr1 + kr3 + 2.0 * kr4;
            num += Ka * m1 - Sb * (double)SEGLEN
                 + h0 * (kr3 + 2.0 * kr4) + h1 * kr4
                 - hD1 * ((double)D * kr1 + (double)(D + 1) * kr0)
                 - hD2 * ((double)D * kr0);
        }
        float mean = (float)(num / (double)SEGLEN);
        if (coord) smY[s] = mean; else smX[s] = mean;
    }
    __syncthreads();

    if (t < 96) {
        int coord = t / NSEG, s = t % NSEG;
        int D = coord ? HEI : WID;
        const float* m = coord ? smY : smX;
        float start = m[SIDX_C];
        float dis = (float)(D / 2) - start;
        float a = rintf((m[s] - start) - dis);
        g_aligned[(b * NSEG + s) * 2 + coord] = (int)a;
    }
    if (t < NSTEP) {
        bool fx = outl(smX, SIDX_C + 1 + t);
        bool fy = outl(smY, SIDX_C + 1 + t);
        s_flag[t] = (fx || fy) ? 1 : 0;
    }
    __syncthreads();
    if (t == 0) {
        unsigned long long m = 1ull;                 // row 0 always active
        for (int r = 1; r < ROWS_USED; r++)
            if (!s_flag[r - 1]) m |= 1ull << r;
        g_actmask[b] = m;
    }
}

// ---------------- K3: per-row byte COUNT map (shared atomics) -> bitmap + hist8 ----------------
__global__ void __launch_bounds__(1024) k_hist2d() {
    extern __shared__ unsigned swords[];               // HW/4 = 19200 ints (byte counters)
    int b = blockIdx.x / ROWS_USED, row = blockIdx.x % ROWS_USED;
    if (!((g_actmask[b] >> row) & 1ull)) return;       // inactive: never read
    int t = threadIdx.x;

    // prefetch this thread's events (hide LDG behind zeroing)
    const uint4* pk4 = (const uint4*)(g_packed + ((size_t)b * ROWS_USED + row) * SEGLEN);
    uint4 e0 = pk4[t];
    uint4 e1 = pk4[t + 1024];

    // zero counter map
    uint4* s4 = (uint4*)swords;
    uint4 z = make_uint4(0u, 0u, 0u, 0u);
    #pragma unroll
    for (int i = t; i < HW / 16; i += 1024) s4[i] = z;
    __syncthreads();

    int s = row + SIDX_C;
    int ax = g_aligned[(b * NSEG + s) * 2];
    int ay = g_aligned[(b * NSEG + s) * 2 + 1];

    unsigned ev[8] = { e0.x, e0.y, e0.z, e0.w, e1.x, e1.y, e1.z, e1.w };
    #pragma unroll
    for (int k = 0; k < 8; k++) {
        int x = (int)(ev[k] & 511u), y = (int)(ev[k] >> 9);
        int xx = min(max(x - ax, 0), WID - 1);
        int yy = min(max(y - ay, 0), HEI - 1);
        int p = yy * WID + xx;
        atomicAdd(&swords[p >> 2], 1u << (8 * (p & 3)));
    }
    __syncthreads();

    // pack: bitmap word (byte!=0) -> g_raw;  byte counts -> g_hist8 (streaming)
    unsigned* dst = g_raw + (size_t)(b * ROWS_USED + row) * NWORD;
    uint4* h4 = (uint4*)(g_hist8 + (size_t)(b * ROWS_USED + row) * HW);
    #pragma unroll
    for (int w = t; w < NWORD; w += 1024) {
        uint4 lo = s4[w * 2];
        uint4 hi = s4[w * 2 + 1];
        unsigned us[8] = { lo.x, lo.y, lo.z, lo.w, hi.x, hi.y, hi.z, hi.w };
        unsigned m = 0u;
        #pragma unroll
        for (int j = 0; j < 8; j++) {
            unsigned u = us[j];
            m |= (unsigned)(( u         & 255u) != 0u) << (4 * j)
              |  (unsigned)(((u >> 8 )  & 255u) != 0u) << (4 * j + 1)
              |  (unsigned)(((u >> 16)  & 255u) != 0u) << (4 * j + 2)
              |  (unsigned)( (u >> 24)          != 0u) << (4 * j + 3);
        }
        dst[w] = m;
        __stcs(h4 + w * 2,     lo);                    // evict-first: don't wash L2
        __stcs(h4 + w * 2 + 1, hi);
    }
}

// ---------------- K4: FUSED prefix popcounts + decision + conf (rows held in registers) ----------------
__global__ void __launch_bounds__(256) k_prefconf() {
    __shared__ int s_cnt[ROWS_USED];
    __shared__ int s_last;
    __shared__ unsigned long long s_ctb;
    __shared__ int s_ls, s_lq;
    int b = blockIdx.x / WBLK, wb = blockIdx.x % WBLK;
    int t = threadIdx.x;
    int w = wb * 256 + t;
    bool val = (w < NWORD);
    const unsigned* rawb = g_raw + (size_t)b * ROWS_USED * NWORD + (val ? w : 0);
    unsigned long long mask = g_actmask[b];

    unsigned wv[ROWS_USED];
    #pragma unroll
    for (int r = 0; r < ROWS_USED; r++)
        wv[r] = (val && ((mask >> r) & 1ull)) ? rawb[(size_t)r * NWORD] : 0u;

    if (t < ROWS_USED) s_cnt[t] = 0;
    if (t == 0) { s_ls = 0; s_lq = 0; }
    __syncthreads();

    // ---- prefix-union popcounts ----
    {
        unsigned u = 0u;
        #pragma unroll
        for (int r = 0; r < ROWS_USED; r++) {
            u |= wv[r];
            unsigned c = __reduce_add_sync(0xffffffffu, (unsigned)__popc(u));
            if ((t & 31) == 0) atomicAdd(&s_cnt[r], (int)c);
        }
    }
    __syncthreads();
    if (t < ROWS_USED) atomicAdd(&g_cnt[b * ROWS_USED + t], s_cnt[t]);

    // ---- last block of batch b: decision masks, publish contrib via atomic ----
    __threadfence();
    __syncthreads();
    if (t == 0) s_last = atomicAdd(&g_done2[b], 1);
    __syncthreads();
    if (s_last == WBLK - 1) {
        if (t < ROWS_USED) s_cnt[t] = __ldcg(&g_cnt[b * ROWS_USED + t]);
        __syncthreads();
        if (t == 0) {
            unsigned long long contrib = 0ull, applied = 1ull;
            int prev = s_cnt[0];
            bool stopped = false;
            #pragma unroll
            for (int r = 1; r < ROWS_USED; r++) {
                if (!((mask >> r) & 1ull) || stopped) continue;
                int cur = s_cnt[r];
                int newc = cur - prev;
                float ratio = (float)newc / (float)cur;
                contrib |= 1ull << r;
                if (ratio < 0.01f) { stopped = true; }
                else { applied |= 1ull << r; prev = cur; }
            }
            g_apl[b] = applied;
            __threadfence();
            atomicExch(&g_ctb[b], contrib);
        }
    }

    // ---- all blocks: wait for contrib mask (safe: all 320 blocks co-resident) ----
    if (t == 0) {
        unsigned long long c;
        while ((c = atomicAdd(&g_ctb[b], 0ull)) == SENT) { }
        s_ctb = c;
    }
    __syncthreads();
    unsigned long long contrib = s_ctb;

    // ---- conf bitplanes from REGISTER-resident rows (no re-read) ----
    unsigned A = wv[0], B = 0xffffffffu;
    unsigned p0 = 0, p1 = 0, p2 = 0, p3 = 0, p4 = 0, p5 = 0;
    #pragma unroll
    for (int r = 1; r < ROWS_USED; r++) {
        if ((contrib >> r) & 1ull) {                   // uniform branch
            unsigned carry = wv[r] & A & B, nx;
            nx = p0 & carry; p0 ^= carry; carry = nx;
            nx = p1 & carry; p1 ^= carry; carry = nx;
            nx = p2 & carry; p2 ^= carry; carry = nx;
            nx = p3 & carry; p3 ^= carry; carry = nx;
            nx = p4 & carry; p4 ^= carry; carry = nx;
            p5 ^= carry;
            B = A; A |= wv[r];
        }
    }

    int ls = 0, lq = 0;
    unsigned vb[8];
    #pragma unroll
    for (int q = 0; q < 8; q++) {
        unsigned pk = 0;
        #pragma unroll
        for (int k = 0; k < 4; k++) {
            int bit = q * 4 + k;
            int v =  (int)((p0 >> bit) & 1u)
                  | ((int)((p1 >> bit) & 1u) << 1)
                  | ((int)((p2 >> bit) & 1u) << 2)
                  | ((int)((p3 >> bit) & 1u) << 3)
                  | ((int)((p4 >> bit) & 1u) << 4)
                  | ((int)((p5 >> bit) & 1u) << 5);
            pk |= (unsigned)v << (k * 8);
            ls += v; lq += v * v;
        }
        vb[q] = pk;
    }
    if (val) {
        uint4* dst = (uint4*)(g_conf8 + (size_t)b * HW + (size_t)w * 32);
        dst[0] = make_uint4(vb[0], vb[1], vb[2], vb[3]);
        dst[1] = make_uint4(vb[4], vb[5], vb[6], vb[7]);
    }
    for (int o = 16; o; o >>= 1) {
        ls += __shfl_down_sync(0xffffffffu, ls, o);
        lq += __shfl_down_sync(0xffffffffu, lq, o);
    }
    if ((t & 31) == 0) { atomicAdd(&s_ls, ls); atomicAdd(&s_lq, lq); }
    __syncthreads();
    if (t == 0) { atomicAdd(&g_stat[b * 4], s_ls); atomicAdd(&g_stat[b * 4 + 1], s_lq); }
}

// ---------------- K5: cont_sum blocks + conf-channel normalize blocks in one launch ----------------
__global__ void __launch_bounds__(256) k_cont(float* __restrict__ out) {
    __shared__ int s_ls, s_lq;
    int t = threadIdx.x;

    if (blockIdx.x < NB * 20) {
        // ===== cont_sum role: packed 16-bit lane accumulation =====
        int b = blockIdx.x / 20, blk = blockIdx.x % 20;
        int idx = blk * 256 + t;                       // uint4 group of 16 pixels
        bool val = (idx < HW / 16);
        unsigned long long applied = g_apl[b];

        if (t == 0) { s_ls = 0; s_lq = 0; }
        __syncthreads();

        unsigned accE[4] = {0,0,0,0}, accO[4] = {0,0,0,0};
        if (val) {
            const unsigned char* hb = g_hist8 + (size_t)b * ROWS_USED * HW + (size_t)idx * 16;
            #pragma unroll
            for (int r = 0; r < ROWS_USED; r++) {
                if ((applied >> r) & 1ull) {           // uniform branch
                    uint4 h = __ldcs((const uint4*)(hb + (size_t)r * HW));
                    unsigned us[4] = { h.x, h.y, h.z, h.w };
                    #pragma unroll
                    for (int j = 0; j < 4; j++) {
                        accE[j] +=  us[j]       & 0x00FF00FFu;
                        accO[j] += (us[j] >> 8) & 0x00FF00FFu;
                    }
                }
            }
        }

        int ls = 0, lq = 0;
        int4 outv[4];
        #pragma unroll
        for (int j = 0; j < 4; j++) {
            int v0 = (int)(accE[j] & 0xFFFFu);
            int v1 = (int)(accO[j] & 0xFFFFu);
            int v2 = (int)(accE[j] >> 16);
            int v3 = (int)(accO[j] >> 16);
            outv[j] = make_int4(v0, v1, v2, v3);
            ls += v0 + v1 + v2 + v3;
            lq += v0 * v0 + v1 * v1 + v2 * v2 + v3 * v3;
        }

        if (val) {
            int4* dst = (int4*)(g_cont + (size_t)b * HW + (size_t)idx * 16);
            #pragma unroll
            for (int j = 0; j < 4; j++) dst[j] = outv[j];
        }

        for (int o = 16; o; o >>= 1) {
            ls += __shfl_down_sync(0xffffffffu, ls, o);
            lq += __shfl_down_sync(0xffffffffu, lq, o);
        }
        if ((t & 31) == 0) { atomicAdd(&s_ls, ls); atomicAdd(&s_lq, lq); }
        __syncthreads();
        if (t == 0) { atomicAdd(&g_stat[b * 4 + 2], s_ls); atomicAdd(&g_stat[b * 4 + 3], s_lq); }
    } else {
        // ===== conf-channel normalize (stats ready from k_prefconf) =====
        int b = blockIdx.x - NB * 20;
        double n = (double)HW;
        double sum = (double)g_stat[b * 4];
        double sq  = (double)g_stat[b * 4 + 1];
        double mu = sum / n;
        double var = (sq - sum * sum / n) / (n - 1.0);
        if (var < 0.0) var = 0.0;
        float clampv = (float)(mu + 3.0 * sqrt(var));
        float* op = out + ((size_t)b * 2 + 1) * HW;
        const uint4* s4 = (const uint4*)(g_conf8 + (size_t)b * HW);
        for (int q = t; q < HW / 16; q += 256) {
            uint4 pk = s4[q];
            unsigned ws[4] = { pk.x, pk.y, pk.z, pk.w };
            float4* d4 = (float4*)(op + q * 16);
            #pragma unroll
            for (int j = 0; j < 4; j++) {
                float4 f;
                f.x = fminf((float)( ws[j]        & 255u), clampv) / clampv;
                f.y = fminf((float)((ws[j] >> 8 ) & 255u), clampv) / clampv;
                f.z = fminf((float)((ws[j] >> 16) & 255u), clampv) / clampv;
                f.w = fminf((float)( ws[j] >> 24        ), clampv) / clampv;
                d4[j] = f;
            }
        }
    }
}

// ---------------- K6: normalize container channel only ----------------
__global__ void __launch_bounds__(512) k_norm(float* __restrict__ out) {
    int b = blockIdx.x;
    int t = threadIdx.x;
    double n = (double)HW;

    double sum = (double)g_stat[b * 4 + 2];
    double sq  = (double)g_stat[b * 4 + 3];
    double mu = sum / n;
    double var = (sq - sum * sum / n) / (n - 1.0);
    if (var < 0.0) var = 0.0;
    float clampv = (float)(mu + 3.0 * sqrt(var));
    float* op = out + (size_t)b * 2 * HW;

    const int4* s4 = (const int4*)(g_cont + (size_t)b * HW);
    for (int q = t; q < HW / 4; q += 512) {
        int4 v = s4[q];
        float4 f;
        f.x = fminf((float)v.x, clampv) / clampv;
        f.y = fminf((float)v.y, clampv) / clampv;
        f.z = fminf((float)v.z, clampv) / clampv;
        f.w = fminf((float)v.w, clampv) / clampv;
        ((float4*)op)[q] = f;
    }
}

// ---------------- launch ----------------
extern "C" void kernel_launch(void* const* d_in, const int* in_sizes, int n_in,
                              void* d_out, int out_size) {
    const int*   ev   = (const int*)d_in[0];
    const float* kern = (const float*)d_in[1];
    float*       out  = (float*)d_out;
    (void)in_sizes; (void)n_in; (void)out_size;

    cudaFuncSetAttribute(k_hist2d, cudaFuncAttributeMaxDynamicSharedMemorySize, HW);

    k_hist<<<NB * NSEG, 256>>>(ev);
    k_mean<<<NB, 128>>>(kern);
    k_hist2d<<<NB * ROWS_USED, 1024, HW>>>();
    k_prefconf<<<NB * WBLK, 256>>>();
    k_cont<<<NB * 20 + NB, 256>>>(out);
    k_norm<<<NB, 512>>>(out);
}

// round 15
// speedup vs baseline: 1.4190x; 1.4190x over previous
#include <cuda_runtime.h>
#include <cuda_bf16.h>
#include <math.h>

#define NB     32
#define NEV    393216
#define NSEG   48
#define SEGLEN 8192
#define WID    320
#define HEI    240
#define HW     76800
#define NWORD  2400        // HW/32
#define SIDX_C 4
#define EIDX_C 38
#define ROWS_USED 34       // rows 4..37 (row index 0..33)
#define NSTEP  33
#define WBLK   10          // word-blocks per batch (10*256 >= 2400)
#define NSPLIT 4           // k_norm blocks per (batch, channel)

// ---------------- device scratch ----------------
__device__ int                g_mom[NB * NSEG * 10];
__device__ unsigned           g_packed[(size_t)NB * ROWS_USED * SEGLEN]; // (y<<9)|x
__device__ int                g_aligned[NB * NSEG * 2];
__device__ unsigned long long g_actmask[NB];
__device__ unsigned long long g_ctb[NB];                  // contrib mask (pref tail)
__device__ unsigned long long g_apl[NB];                  // applied mask (pref tail)
__device__ int                g_done2[NB];
__device__ int                g_cnt[NB * ROWS_USED];
__device__ int                g_stat[NB * 4];   // conf sum, conf sq, cont sum, cont sq (int exact)
__device__ unsigned           g_raw[(size_t)NB * ROWS_USED * NWORD];     // per-row bitmaps
__device__ unsigned char      g_hist8[(size_t)NB * ROWS_USED * HW];      // per-row byte counts
__device__ unsigned char      g_conf8[(size_t)NB * HW];
__device__ int                g_cont[(size_t)NB * HW];

// ---------------- K1: histogram moments + packed coords ----------------
__global__ void __launch_bounds__(256) k_hist(const int* __restrict__ ev) {
    __shared__ int shx[WID];
    __shared__ int shy[HEI];
    __shared__ int sm1x, sm1y;
    int bx = blockIdx.x;
    int b = bx / NSEG, s = bx % NSEG;
    int t = threadIdx.x;

    for (int e = t; e < WID; e += 256) shx[e] = 0;
    for (int e = t; e < HEI; e += 256) shy[e] = 0;
    if (t == 0) { sm1x = 0; sm1y = 0; }
    __syncthreads();

    const uint4* evv = (const uint4*)(ev + ((size_t)b * NEV + (size_t)s * SEGLEN) * 5);
    bool wr = (s >= SIDX_C && s < EIDX_C);
    int sp = s - SIDX_C; if (sp < 0) sp = 0;
    uint4* pk4 = (uint4*)(g_packed + ((size_t)b * ROWS_USED + sp) * SEGLEN);

    for (int g = t; g < SEGLEN / 4; g += 256) {
        uint4 a0 = evv[g * 5 + 0];
        uint4 a1 = evv[g * 5 + 1];
        uint4 a2 = evv[g * 5 + 2];
        uint4 a3 = evv[g * 5 + 3];
        uint4 a4 = evv[g * 5 + 4];
        int x0 = (int)a0.x, y0 = (int)a0.y;
        int x1 = (int)a1.y, y1 = (int)a1.z;
        int x2 = (int)a2.z, y2 = (int)a2.w;
        int x3 = (int)a3.w, y3 = (int)a4.x;
        atomicAdd(&shx[x0], 1); atomicAdd(&shy[y0], 1);
        atomicAdd(&shx[x1], 1); atomicAdd(&shy[y1], 1);
        atomicAdd(&shx[x2], 1); atomicAdd(&shy[y2], 1);
        atomicAdd(&shx[x3], 1); atomicAdd(&shy[y3], 1);
        if (wr) {
            uint4 p;
            p.x = (unsigned)((y0 << 9) | x0);
            p.y = (unsigned)((y1 << 9) | x1);
            p.z = (unsigned)((y2 << 9) | x2);
            p.w = (unsigned)((y3 << 9) | x3);
            pk4[g] = p;
        }
    }
    __syncthreads();

    int l1 = 0, l2 = 0;
    for (int e = t; e < WID; e += 256) l1 += e * shx[e];
    for (int e = t; e < HEI; e += 256) l2 += e * shy[e];
    for (int o = 16; o; o >>= 1) {
        l1 += __shfl_down_sync(0xffffffffu, l1, o);
        l2 += __shfl_down_sync(0xffffffffu, l2, o);
    }
    if ((t & 31) == 0) { atomicAdd(&sm1x, l1); atomicAdd(&sm1y, l2); }
    __syncthreads();

    if (t == 0) {
        int* mm = g_mom + (b * NSEG + s) * 10;
        mm[0] = sm1x; mm[1] = shx[0]; mm[2] = shx[1]; mm[3] = shx[WID - 2]; mm[4] = shx[WID - 1];
        mm[5] = sm1y; mm[6] = shy[0]; mm[7] = shy[1]; mm[8] = shy[HEI - 2]; mm[9] = shy[HEI - 1];
    }
}

// ---------------- K2: means + aligned + outlier flags -> active mask ----------------
__device__ __forceinline__ void sort10(float* a) {
    #pragma unroll
    for (int i = 1; i < 10; i++) {
        float v = a[i]; int j = i - 1;
        while (j >= 0 && a[j] > v) { a[j + 1] = a[j]; j--; }
        a[j + 1] = v;
    }
}

__device__ bool outl(const float* m, int i) {
    float w[10], s[10];
    #pragma unroll
    for (int t = 0; t < 10; t++) { w[t] = m[i + t]; s[t] = w[t]; }
    sort10(s);
    float med = 0.5f * (s[4] + s[5]);
    float d0 = fabsf(w[0] - med);
    float ds[10];
    #pragma unroll
    for (int t = 0; t < 10; t++) ds[t] = fabsf(w[t] - med);
    sort10(ds);
    float mad = 0.5f * (ds[4] + ds[5]);
    float mz = (0.6745f * d0) / mad;
    return mz > 3.0f;
}

__global__ void __launch_bounds__(128) k_mean(const float* __restrict__ kern) {
    __shared__ float skk[25];
    __shared__ float smX[NSEG], smY[NSEG];
    __shared__ unsigned char s_flag[NSTEP];
    int b = blockIdx.x, t = threadIdx.x;
    if (t < 25) skk[t] = kern[t];
    if (t < ROWS_USED) g_cnt[b * ROWS_USED + t] = 0;
    if (t < 4) g_stat[b * 4 + t] = 0;
    if (t == 0) g_done2[b] = 0;
    __syncthreads();

    if (t < 96) {
        int coord = t / NSEG, s = t % NSEG;
        int D = coord ? HEI : WID;
        double num = 0.0;
        #pragma unroll
        for (int a = -2; a <= 2; a++) {
            int si = s + a;
            if (si < 0 || si >= NSEG) continue;
            const int* mm = g_mom + (b * NSEG + si) * 10 + coord * 5;
            double m1  = (double)mm[0];
            double h0  = (double)mm[1];
            double h1  = (double)mm[2];
            double hD2 = (double)mm[3];
            double hD1 = (double)mm[4];
            double kr0 = skk[(a + 2) * 5 + 0];
            double kr1 = skk[(a + 2) * 5 + 1];
            double kr2 = skk[(a + 2) * 5 + 2];
            double kr3 = skk[(a + 2) * 5 + 3];
            double kr4 = skk[(a + 2) * 5 + 4];
            double Ka = kr0 + kr1 + kr2 + kr3 + kr4;
            double Sb = -2.0 * kr0 - kr1 + kr3 + 2.0 * kr4;
            num += Ka * m1 - Sb * (double)SEGLEN
                 + h0 * (kr3 + 2.0 * kr4) + h1 * kr4
                 - hD1 * ((double)D * kr1 + (double)(D + 1) * kr0)
                 - hD2 * ((double)D * kr0);
        }
        float mean = (float)(num / (double)SEGLEN);
        if (coord) smY[s] = mean; else smX[s] = mean;
    }
    __syncthreads();

    if (t < 96) {
        int coord = t / NSEG, s = t % NSEG;
        int D = coord ? HEI : WID;
        const float* m = coord ? smY : smX;
        float start = m[SIDX_C];
        float dis = (float)(D / 2) - start;
        float a = rintf((m[s] - start) - dis);
        g_aligned[(b * NSEG + s) * 2 + coord] = (int)a;
    }
    if (t < NSTEP) {
        bool fx = outl(smX, SIDX_C + 1 + t);
        bool fy = outl(smY, SIDX_C + 1 + t);
        s_flag[t] = (fx || fy) ? 1 : 0;
    }
    __syncthreads();
    if (t == 0) {
        unsigned long long m = 1ull;                 // row 0 always active
        for (int r = 1; r < ROWS_USED; r++)
            if (!s_flag[r - 1]) m |= 1ull << r;
        g_actmask[b] = m;
    }
}

// ---------------- K3: per-row byte COUNT map (shared atomics) -> bitmap + hist8 ----------------
__global__ void __launch_bounds__(1024) k_hist2d() {
    extern __shared__ unsigned swords[];               // HW/4 = 19200 ints (byte counters)
    int b = blockIdx.x / ROWS_USED, row = blockIdx.x % ROWS_USED;
    if (!((g_actmask[b] >> row) & 1ull)) return;       // inactive: never read
    int t = threadIdx.x;

    // prefetch this thread's events (hide LDG behind zeroing)
    const uint4* pk4 = (const uint4*)(g_packed + ((size_t)b * ROWS_USED + row) * SEGLEN);
    uint4 e0 = pk4[t];
    uint4 e1 = pk4[t + 1024];

    // zero counter map
    uint4* s4 = (uint4*)swords;
    uint4 z = make_uint4(0u, 0u, 0u, 0u);
    #pragma unroll
    for (int i = t; i < HW / 16; i += 1024) s4[i] = z;
    __syncthreads();

    int s = row + SIDX_C;
    int ax = g_aligned[(b * NSEG + s) * 2];
    int ay = g_aligned[(b * NSEG + s) * 2 + 1];

    unsigned ev[8] = { e0.x, e0.y, e0.z, e0.w, e1.x, e1.y, e1.z, e1.w };
    #pragma unroll
    for (int k = 0; k < 8; k++) {
        int x = (int)(ev[k] & 511u), y = (int)(ev[k] >> 9);
        int xx = min(max(x - ax, 0), WID - 1);
        int yy = min(max(y - ay, 0), HEI - 1);
        int p = yy * WID + xx;
        atomicAdd(&swords[p >> 2], 1u << (8 * (p & 3)));
    }
    __syncthreads();

    // pack: bitmap word (byte!=0) -> g_raw;  byte counts -> g_hist8 (streaming)
    unsigned* dst = g_raw + (size_t)(b * ROWS_USED + row) * NWORD;
    uint4* h4 = (uint4*)(g_hist8 + (size_t)(b * ROWS_USED + row) * HW);
    #pragma unroll
    for (int w = t; w < NWORD; w += 1024) {
        uint4 lo = s4[w * 2];
        uint4 hi = s4[w * 2 + 1];
        unsigned us[8] = { lo.x, lo.y, lo.z, lo.w, hi.x, hi.y, hi.z, hi.w };
        unsigned m = 0u;
        #pragma unroll
        for (int j = 0; j < 8; j++) {
            unsigned u = us[j];
            m |= (unsigned)(( u         & 255u) != 0u) << (4 * j)
              |  (unsigned)(((u >> 8 )  & 255u) != 0u) << (4 * j + 1)
              |  (unsigned)(((u >> 16)  & 255u) != 0u) << (4 * j + 2)
              |  (unsigned)( (u >> 24)          != 0u) << (4 * j + 3);
        }
        dst[w] = m;
        __stcs(h4 + w * 2,     lo);                    // evict-first: don't wash L2
        __stcs(h4 + w * 2 + 1, hi);
    }
}

// ---------------- K4: word-parallel prefix-union popcounts; last block computes decision masks ----------------
__global__ void __launch_bounds__(256) k_pref() {
    __shared__ int s_cnt[ROWS_USED];
    __shared__ int s_last;
    int b = blockIdx.x / WBLK, wb = blockIdx.x % WBLK;
    int t = threadIdx.x;
    int w = wb * 256 + t;
    bool val = (w < NWORD);
    const unsigned* rawb = g_raw + (size_t)b * ROWS_USED * NWORD + (val ? w : 0);
    unsigned long long mask = g_actmask[b];

    unsigned wv[ROWS_USED];
    #pragma unroll
    for (int r = 0; r < ROWS_USED; r++)
        wv[r] = (val && ((mask >> r) & 1ull)) ? rawb[(size_t)r * NWORD] : 0u;

    if (t < ROWS_USED) s_cnt[t] = 0;
    __syncthreads();

    unsigned u = 0u;
    #pragma unroll
    for (int r = 0; r < ROWS_USED; r++) {
        u |= wv[r];
        unsigned c = __reduce_add_sync(0xffffffffu, (unsigned)__popc(u));
        if ((t & 31) == 0) atomicAdd(&s_cnt[r], (int)c);
    }
    __syncthreads();
    if (t < ROWS_USED) atomicAdd(&g_cnt[b * ROWS_USED + t], s_cnt[t]);

    // ---- last block of batch b: compute contrib/applied masks once ----
    __threadfence();
    __syncthreads();
    if (t == 0) s_last = atomicAdd(&g_done2[b], 1);
    __syncthreads();
    if (s_last != WBLK - 1) return;

    // parallel load of final counts (one L2 round-trip, not a serial chain)
    if (t < ROWS_USED) s_cnt[t] = __ldcg(&g_cnt[b * ROWS_USED + t]);
    __syncthreads();
    if (t == 0) {
        unsigned long long contrib = 0ull, applied = 1ull;
        int prev = s_cnt[0];
        bool stopped = false;
        #pragma unroll
        for (int r = 1; r < ROWS_USED; r++) {
            if (!((mask >> r) & 1ull) || stopped) continue;
            int cur = s_cnt[r];
            int newc = cur - prev;
            float ratio = (float)newc / (float)cur;
            contrib |= 1ull << r;
            if (ratio < 0.01f) { stopped = true; }
            else { applied |= 1ull << r; prev = cur; }
        }
        g_ctb[b] = contrib;
        g_apl[b] = applied;
    }
}

// ---------------- K5: one launch, two block roles (conf | cont_sum); low reg pressure ----------------
__global__ void __launch_bounds__(256) k_combo() {
    __shared__ int s_ls, s_lq;
    int t = threadIdx.x;

    if (blockIdx.x < NB * WBLK) {
        // ===== conf role: streaming bitplane accumulation =====
        int b = blockIdx.x / WBLK, wb = blockIdx.x % WBLK;
        int w = wb * 256 + t;
        bool val = (w < NWORD);
        const unsigned* rawb = g_raw + (size_t)b * ROWS_USED * NWORD + (val ? w : 0);
        unsigned long long contrib = g_ctb[b];

        if (t == 0) { s_ls = 0; s_lq = 0; }
        __syncthreads();

        unsigned A = val ? rawb[0] : 0u;
        unsigned B = 0xffffffffu;
        unsigned p0 = 0, p1 = 0, p2 = 0, p3 = 0, p4 = 0, p5 = 0;
        #pragma unroll
        for (int r = 1; r < ROWS_USED; r++) {
            if ((contrib >> r) & 1ull) {                   // uniform branch
                unsigned wr2 = val ? rawb[(size_t)r * NWORD] : 0u;
                unsigned carry = wr2 & A & B, nx;
                nx = p0 & carry; p0 ^= carry; carry = nx;
                nx = p1 & carry; p1 ^= carry; carry = nx;
                nx = p2 & carry; p2 ^= carry; carry = nx;
                nx = p3 & carry; p3 ^= carry; carry = nx;
                nx = p4 & carry; p4 ^= carry; carry = nx;
                p5 ^= carry;
                B = A; A |= wr2;
            }
        }

        int ls = 0, lq = 0;
        unsigned vb[8];
        #pragma unroll
        for (int q = 0; q < 8; q++) {
            unsigned pk = 0;
            #pragma unroll
            for (int k = 0; k < 4; k++) {
                int bit = q * 4 + k;
                int v =  (int)((p0 >> bit) & 1u)
                      | ((int)((p1 >> bit) & 1u) << 1)
                      | ((int)((p2 >> bit) & 1u) << 2)
                      | ((int)((p3 >> bit) & 1u) << 3)
                      | ((int)((p4 >> bit) & 1u) << 4)
                      | ((int)((p5 >> bit) & 1u) << 5);
                pk |= (unsigned)v << (k * 8);
                ls += v; lq += v * v;
            }
            vb[q] = pk;
        }
        if (val) {
            uint4* dst = (uint4*)(g_conf8 + (size_t)b * HW + (size_t)w * 32);
            dst[0] = make_uint4(vb[0], vb[1], vb[2], vb[3]);
            dst[1] = make_uint4(vb[4], vb[5], vb[6], vb[7]);
        }
        for (int o = 16; o; o >>= 1) {
            ls += __shfl_down_sync(0xffffffffu, ls, o);
            lq += __shfl_down_sync(0xffffffffu, lq, o);
        }
        if ((t & 31) == 0) { atomicAdd(&s_ls, ls); atomicAdd(&s_lq, lq); }
        __syncthreads();
        if (t == 0) { atomicAdd(&g_stat[b * 4], s_ls); atomicAdd(&g_stat[b * 4 + 1], s_lq); }
    } else {
        // ===== cont_sum role: packed 16-bit lane accumulation =====
        int bi = blockIdx.x - NB * WBLK;
        int b = bi / 20, blk = bi % 20;
        int idx = blk * 256 + t;                       // uint4 group of 16 pixels
        bool val = (idx < HW / 16);
        unsigned long long applied = g_apl[b];

        if (t == 0) { s_ls = 0; s_lq = 0; }
        __syncthreads();

        // accE[j]: 16-bit lanes for bytes 0,2 of word j; accO[j]: bytes 1,3
        unsigned accE[4] = {0,0,0,0}, accO[4] = {0,0,0,0};

        if (val) {
            const unsigned char* hb = g_hist8 + (size_t)b * ROWS_USED * HW + (size_t)idx * 16;
            #pragma unroll
            for (int r = 0; r < ROWS_USED; r++) {
                if ((applied >> r) & 1ull) {           // uniform branch
                    uint4 h = __ldcs((const uint4*)(hb + (size_t)r * HW));
                    unsigned us[4] = { h.x, h.y, h.z, h.w };
                    #pragma unroll
                    for (int j = 0; j < 4; j++) {
                        accE[j] +=  us[j]       & 0x00FF00FFu;
                        accO[j] += (us[j] >> 8) & 0x00FF00FFu;
                    }
                }
            }
        }

        int ls = 0, lq = 0;
        int4 outv[4];
        #pragma unroll
        for (int j = 0; j < 4; j++) {
            int v0 = (int)(accE[j] & 0xFFFFu);
            int v1 = (int)(accO[j] & 0xFFFFu);
            int v2 = (int)(accE[j] >> 16);
            int v3 = (int)(accO[j] >> 16);
            outv[j] = make_int4(v0, v1, v2, v3);
            ls += v0 + v1 + v2 + v3;
            lq += v0 * v0 + v1 * v1 + v2 * v2 + v3 * v3;
        }

        if (val) {
            int4* dst = (int4*)(g_cont + (size_t)b * HW + (size_t)idx * 16);
            #pragma unroll
            for (int j = 0; j < 4; j++) dst[j] = outv[j];
        }

        for (int o = 16; o; o >>= 1) {
            ls += __shfl_down_sync(0xffffffffu, ls, o);
            lq += __shfl_down_sync(0xffffffffu, lq, o);
        }
        if ((t & 31) == 0) { atomicAdd(&s_ls, ls); atomicAdd(&s_lq, lq); }
        __syncthreads();
        if (t == 0) { atomicAdd(&g_stat[b * 4 + 2], s_ls); atomicAdd(&g_stat[b * 4 + 3], s_lq); }
    }
}

// ---------------- K6: normalize both channels, 4 blocks per (batch, channel) ----------------
__global__ void __launch_bounds__(512) k_norm(float* __restrict__ out) {
    int blk = blockIdx.x;
    int part = blk & (NSPLIT - 1);
    int pass = (blk >> 2) & 1;
    int b = blk >> 3;
    int t = threadIdx.x;
    double n = (double)HW;

    double sum = (double)g_stat[b * 4 + (pass ? 0 : 2)];
    double sq  = (double)g_stat[b * 4 + (pass ? 1 : 3)];
    double mu = sum / n;
    double var = (sq - sum * sum / n) / (n - 1.0);
    if (var < 0.0) var = 0.0;
    float clampv = (float)(mu + 3.0 * sqrt(var));
    float* op = out + ((size_t)b * 2 + pass) * HW;

    if (pass == 1) {
        const int NG = HW / 16;                       // 4800 uint4 groups
        const int per = NG / NSPLIT;                  // 1200
        int lo = part * per, hi = lo + per;
        const uint4* s4 = (const uint4*)(g_conf8 + (size_t)b * HW);
        for (int q = lo + t; q < hi; q += 512) {
            uint4 pk = s4[q];
            unsigned ws[4] = { pk.x, pk.y, pk.z, pk.w };
            float4* d4 = (float4*)(op + q * 16);
            #pragma unroll
            for (int j = 0; j < 4; j++) {
                float4 f;
                f.x = fminf((float)( ws[j]        & 255u), clampv) / clampv;
                f.y = fminf((float)((ws[j] >> 8 ) & 255u), clampv) / clampv;
                f.z = fminf((float)((ws[j] >> 16) & 255u), clampv) / clampv;
                f.w = fminf((float)( ws[j] >> 24        ), clampv) / clampv;
                d4[j] = f;
            }
        }
    } else {
        const int NG = HW / 4;                        // 19200 int4 groups
        const int per = NG / NSPLIT;                  // 4800
        int lo = part * per, hi = lo + per;
        const int4* s4 = (const int4*)(g_cont + (size_t)b * HW);
        for (int q = lo + t; q < hi; q += 512) {
            int4 v = s4[q];
            float4 f;
            f.x = fminf((float)v.x, clampv) / clampv;
            f.y = fminf((float)v.y, clampv) / clampv;
            f.z = fminf((float)v.z, clampv) / clampv;
            f.w = fminf((float)v.w, clampv) / clampv;
            ((float4*)op)[q] = f;
        }
    }
}

// ---------------- launch ----------------
extern "C" void kernel_launch(void* const* d_in, const int* in_sizes, int n_in,
                              void* d_out, int out_size) {
    const int*   ev   = (const int*)d_in[0];
    const float* kern = (const float*)d_in[1];
    float*       out  = (float*)d_out;
    (void)in_sizes; (void)n_in; (void)out_size;

    cudaFuncSetAttribute(k_hist2d, cudaFuncAttributeMaxDynamicSharedMemorySize, HW);

    k_hist<<<NB * NSEG, 256>>>(ev);
    k_mean<<<NB, 128>>>(kern);
    k_hist2d<<<NB * ROWS_USED, 1024, HW>>>();
    k_pref<<<NB * WBLK, 256>>>();
    k_combo<<<NB * WBLK + NB * 20, 256>>>();
    k_norm<<<NB * 2 * NSPLIT, 512>>>(out);
}